// round 6
// baseline (speedup 1.0000x reference)
#include <cuda_runtime.h>
#include <math_constants.h>

#define N_BINS 15
#define RPW 8          // rows per warp per iter (one row per 4-lane segment)

// Global scratch (no allocation allowed). Zeroed at module load; the fused
// finalizer re-zeroes after each use, so every graph replay starts from zero.
__device__ float    g_cnt[N_BINS];
__device__ float    g_conf[N_BINS];
__device__ float    g_acc[N_BINS];
__device__ unsigned g_done;

__device__ __forceinline__ float ex2f(float x) {
    float r;
    asm volatile("ex2.approx.f32 %0, %1;" : "=f"(r) : "f"(x));
    return r;
}

#define LOG2E 1.4426950408889634f

// 4 lanes per row: lane covers 32 floats (8 float4, stride-4 within the row).
// A warp processes 8 consecutive rows per iteration (4 KB contiguous).
// Reduction = 2 butterfly levels across the 4-lane segment — one SHFL
// instruction reduces all 8 rows at once.
// No atomics in the hot loop: lane b (<15) owns register accumulators for bin b.
__global__ void __launch_bounds__(256, 5) mce_main_kernel(
    const float4* __restrict__ logits4,   // [nrows * 32] float4
    const float*  __restrict__ logits,    // same buffer, scalar view
    const int*    __restrict__ labels,    // [nrows]
    float*        __restrict__ out,
    int nrows)
{
    __shared__ float s_cnt[N_BINS];
    __shared__ float s_conf[N_BINS];
    __shared__ float s_acc[N_BINS];
    __shared__ bool  s_last;

    int tid = threadIdx.x;
    if (tid < N_BINS) {
        s_cnt[tid]  = 0.0f;
        s_conf[tid] = 0.0f;
        s_acc[tid]  = 0.0f;
    }
    __syncthreads();

    int lane   = tid & 31;
    int seg    = lane >> 2;                // row within group (0..7)
    int sub    = lane & 3;                 // lane within row segment
    int warp   = (blockIdx.x * blockDim.x + tid) >> 5;
    int nwarps = (gridDim.x * blockDim.x) >> 5;

    float r_cnt = 0.0f, r_conf = 0.0f, r_acc = 0.0f;

    for (int base = warp * RPW; base < nrows; base += nwarps * RPW) {
        int row  = base + seg;
        int rowc = (row < nrows) ? row : (nrows - 1);   // clamp tail

        // label for my segment's row (8 consecutive ints, broadcast in segment)
        int lab = labels[rowc];

        // front-batched row loads: 8 LDG.128 per lane, warp covers 4 KB
        float4 v[RPW];
        const float4* rp = logits4 + (size_t)rowc * 32 + sub;
        #pragma unroll
        for (int i = 0; i < RPW; i++) v[i] = rp[4 * i];

        // label's logit (hits the L1 lines the row loads fetch; MSHR-merged)
        float lv = logits[(size_t)rowc * 128 + lab];

        // ---- per-lane max over 32 values, tree ----
        float pm[RPW];
        #pragma unroll
        for (int i = 0; i < RPW; i++)
            pm[i] = fmaxf(fmaxf(v[i].x, v[i].y), fmaxf(v[i].z, v[i].w));
        float m = fmaxf(fmaxf(fmaxf(pm[0], pm[1]), fmaxf(pm[2], pm[3])),
                        fmaxf(fmaxf(pm[4], pm[5]), fmaxf(pm[6], pm[7])));
        // segment butterfly: 2 levels, all 8 rows reduced per instruction
        m = fmaxf(m, __shfl_xor_sync(0xffffffffu, m, 1));
        m = fmaxf(m, __shfl_xor_sync(0xffffffffu, m, 2));

        // ---- sum of exp(x - m) = ex2(x*log2e - m*log2e) ----
        float mL = m * LOG2E;
        float ps[RPW];
        #pragma unroll
        for (int i = 0; i < RPW; i++) {
            float e0 = ex2f(fmaf(v[i].x, LOG2E, -mL));
            float e1 = ex2f(fmaf(v[i].y, LOG2E, -mL));
            float e2 = ex2f(fmaf(v[i].z, LOG2E, -mL));
            float e3 = ex2f(fmaf(v[i].w, LOG2E, -mL));
            ps[i] = (e0 + e1) + (e2 + e3);
        }
        float s = ((ps[0] + ps[1]) + (ps[2] + ps[3]))
                + ((ps[4] + ps[5]) + (ps[6] + ps[7]));
        s += __shfl_xor_sync(0xffffffffu, s, 1);
        s += __shfl_xor_sync(0xffffffffu, s, 2);

        float conf = __fdividef(1.0f, s);      // = exp(max)/sum exp

        // one ballot covers all 8 rows' accuracy checks (ties: measure zero)
        unsigned b = __ballot_sync(0xffffffffu, lv == m);

        int nr = min(RPW, nrows - base);
        #pragma unroll
        for (int r = 0; r < RPW; r++) {
            float cf = __shfl_sync(0xffffffffu, conf, r * 4);
            // bin i covers (i/15, (i+1)/15]; conf >= 1/128 -> bin >= 0 always
            int bin = min(__float2int_ru(cf * (float)N_BINS) - 1, N_BINS - 1);
            if (bin == lane && r < nr) {
                r_cnt  += 1.0f;
                r_conf += cf;
                r_acc  += (float)((b >> (4 * r)) & 1u);
            }
        }
    }

    // ---- flush: registers -> shared -> global (once per block) ----
    if (lane < N_BINS && r_cnt != 0.0f) {
        atomicAdd(&s_cnt[lane],  r_cnt);
        atomicAdd(&s_conf[lane], r_conf);
        atomicAdd(&s_acc[lane],  r_acc);
    }
    __syncthreads();
    if (tid < N_BINS) {
        float c = s_cnt[tid];
        if (c != 0.0f) {
            atomicAdd(&g_cnt[tid],  c);
            atomicAdd(&g_conf[tid], s_conf[tid]);
            atomicAdd(&g_acc[tid],  s_acc[tid]);
        }
    }
    __threadfence();
    __syncthreads();

    // ---- last block finalizes (fused; no second launch) ----
    if (tid == 0)
        s_last = (atomicAdd(&g_done, 1u) == gridDim.x - 1u);
    __syncthreads();
    if (s_last && tid == 0) {
        volatile float* vc = g_cnt;
        volatile float* vp = g_conf;
        volatile float* va = g_acc;
        float mce = -CUDART_INF_F;
        #pragma unroll
        for (int i = 0; i < N_BINS; i++) {
            float c    = vc[i];
            float prob = 0.0f, accu = 0.0f;
            if (c > 0.0f) {
                prob = vp[i] / c;
                accu = va[i] / c;
                float gap = fabsf(prob - accu);
                if (gap > mce) mce = gap;
            }
            out[1 + i]          = prob;
            out[1 + N_BINS + i] = accu;
            vc[i] = 0.0f; vp[i] = 0.0f; va[i] = 0.0f;   // reset for next replay
        }
        out[0] = mce;
        g_done = 0u;
    }
}

extern "C" void kernel_launch(void* const* d_in, const int* in_sizes, int n_in,
                              void* d_out, int out_size) {
    const float4* logits4 = (const float4*)d_in[0];
    const float*  logits  = (const float*)d_in[0];
    const int*    labels  = (const int*)d_in[1];
    int nrows = in_sizes[1];               // labels element count == N rows

    // 5 CTAs/SM x 148 SMs = 740 blocks resident; grid-stride over row groups
    mce_main_kernel<<<740, 256>>>(logits4, logits, labels, (float*)d_out, nrows);
}

// round 7
// speedup vs baseline: 1.0304x; 1.0304x over previous
#include <cuda_runtime.h>
#include <math_constants.h>

#define N_BINS 15
#define RPW 8          // rows per warp per iter (2 rows per lane, 4 segments)

// Global scratch (no allocation allowed). Zeroed at module load; the fused
// finalizer re-zeroes after each use, so every graph replay starts from zero.
__device__ float    g_cnt[N_BINS];
__device__ float    g_conf[N_BINS];
__device__ float    g_acc[N_BINS];
__device__ unsigned g_done;

__device__ __forceinline__ float ex2f(float x) {
    float r;
    asm volatile("ex2.approx.f32 %0, %1;" : "=f"(r) : "f"(x));
    return r;
}

#define LOG2E 1.4426950408889634f

// 8 lanes per row, 2 rows per lane: lane covers 16 floats of row A and 16 of
// row B (4 float4 each, stride-8 so each LDG.128 reads 4 FULL 128B lines).
// A warp processes 8 consecutive rows per iteration (4 KB contiguous,
// front-batched -> MLP_p1 = 8 full-line LDGs).
// Cross-lane reduction: 3 butterfly levels within the 8-lane segment.
// No atomics in the hot loop: lane b (<15) owns register accumulators for bin b.
__global__ void __launch_bounds__(256) mce_main_kernel(
    const float4* __restrict__ logits4,   // [nrows * 32] float4
    const float*  __restrict__ logits,    // same buffer, scalar view
    const int*    __restrict__ labels,    // [nrows]
    float*        __restrict__ out,
    int nrows)
{
    __shared__ float s_cnt[N_BINS];
    __shared__ float s_conf[N_BINS];
    __shared__ float s_acc[N_BINS];
    __shared__ bool  s_last;

    int tid = threadIdx.x;
    if (tid < N_BINS) {
        s_cnt[tid]  = 0.0f;
        s_conf[tid] = 0.0f;
        s_acc[tid]  = 0.0f;
    }
    __syncthreads();

    int lane   = tid & 31;
    int seg    = lane >> 3;                // segment 0..3
    int sub    = lane & 7;                 // lane within 8-lane segment
    int warp   = (blockIdx.x * blockDim.x + tid) >> 5;
    int nwarps = (gridDim.x * blockDim.x) >> 5;

    float r_cnt = 0.0f, r_conf = 0.0f, r_acc = 0.0f;

    for (int base = warp * RPW; base < nrows; base += nwarps * RPW) {
        int rowA = base + seg;             // rows 0..3 of the group
        int rowB = base + seg + 4;         // rows 4..7 of the group
        int rowAc = (rowA < nrows) ? rowA : (nrows - 1);
        int rowBc = (rowB < nrows) ? rowB : (nrows - 1);

        int labA = labels[rowAc];
        int labB = labels[rowBc];

        // front-batched loads: 8 full-line LDG.128 per warp-iter (4 KB)
        float4 vA[4], vB[4];
        const float4* rpA = logits4 + (size_t)rowAc * 32 + sub;
        const float4* rpB = logits4 + (size_t)rowBc * 32 + sub;
        #pragma unroll
        for (int i = 0; i < 4; i++) vA[i] = rpA[8 * i];
        #pragma unroll
        for (int i = 0; i < 4; i++) vB[i] = rpB[8 * i];

        // label logits (same lines as the row loads; MSHR-merged, broadcast)
        float lvA = logits[(size_t)rowAc * 128 + labA];
        float lvB = logits[(size_t)rowBc * 128 + labB];

        // ---- per-lane max over 16 values each row ----
        float mA, mB;
        {
            float p0 = fmaxf(fmaxf(vA[0].x, vA[0].y), fmaxf(vA[0].z, vA[0].w));
            float p1 = fmaxf(fmaxf(vA[1].x, vA[1].y), fmaxf(vA[1].z, vA[1].w));
            float p2 = fmaxf(fmaxf(vA[2].x, vA[2].y), fmaxf(vA[2].z, vA[2].w));
            float p3 = fmaxf(fmaxf(vA[3].x, vA[3].y), fmaxf(vA[3].z, vA[3].w));
            mA = fmaxf(fmaxf(p0, p1), fmaxf(p2, p3));
            float q0 = fmaxf(fmaxf(vB[0].x, vB[0].y), fmaxf(vB[0].z, vB[0].w));
            float q1 = fmaxf(fmaxf(vB[1].x, vB[1].y), fmaxf(vB[1].z, vB[1].w));
            float q2 = fmaxf(fmaxf(vB[2].x, vB[2].y), fmaxf(vB[2].z, vB[2].w));
            float q3 = fmaxf(fmaxf(vB[3].x, vB[3].y), fmaxf(vB[3].z, vB[3].w));
            mB = fmaxf(fmaxf(q0, q1), fmaxf(q2, q3));
        }
        // 3-level segment butterflies, two rows interleaved
        #pragma unroll
        for (int off = 1; off <= 4; off <<= 1) {
            mA = fmaxf(mA, __shfl_xor_sync(0xffffffffu, mA, off));
            mB = fmaxf(mB, __shfl_xor_sync(0xffffffffu, mB, off));
        }

        // ---- sum of exp(x - m) = ex2(x*log2e - m*log2e) ----
        float mLA = mA * LOG2E, mLB = mB * LOG2E;
        float sA = 0.0f, sB = 0.0f;
        #pragma unroll
        for (int i = 0; i < 4; i++) {
            float a0 = ex2f(fmaf(vA[i].x, LOG2E, -mLA));
            float a1 = ex2f(fmaf(vA[i].y, LOG2E, -mLA));
            float a2 = ex2f(fmaf(vA[i].z, LOG2E, -mLA));
            float a3 = ex2f(fmaf(vA[i].w, LOG2E, -mLA));
            sA += (a0 + a1) + (a2 + a3);
            float b0 = ex2f(fmaf(vB[i].x, LOG2E, -mLB));
            float b1 = ex2f(fmaf(vB[i].y, LOG2E, -mLB));
            float b2 = ex2f(fmaf(vB[i].z, LOG2E, -mLB));
            float b3 = ex2f(fmaf(vB[i].w, LOG2E, -mLB));
            sB += (b0 + b1) + (b2 + b3);
        }
        #pragma unroll
        for (int off = 1; off <= 4; off <<= 1) {
            sA += __shfl_xor_sync(0xffffffffu, sA, off);
            sB += __shfl_xor_sync(0xffffffffu, sB, off);
        }

        float confA = __fdividef(1.0f, sA);    // = exp(max)/sum exp
        float confB = __fdividef(1.0f, sB);

        // accuracy ballots: row r (0..3) -> bit 8r of bA; row 4+r -> bit 8r of bB
        unsigned bA = __ballot_sync(0xffffffffu, lvA == mA);
        unsigned bB = __ballot_sync(0xffffffffu, lvB == mB);

        int nr = min(RPW, nrows - base);
        #pragma unroll
        for (int r = 0; r < RPW; r++) {
            float cf = (r < 4)
                     ? __shfl_sync(0xffffffffu, confA, (r & 3) * 8)
                     : __shfl_sync(0xffffffffu, confB, (r & 3) * 8);
            unsigned abit = (r < 4) ? ((bA >> (8 * (r & 3))) & 1u)
                                    : ((bB >> (8 * (r & 3))) & 1u);
            // bin i covers (i/15, (i+1)/15]
            int bin = min(__float2int_ru(cf * (float)N_BINS) - 1, N_BINS - 1);
            if (bin == lane && r < nr) {
                r_cnt  += 1.0f;
                r_conf += cf;
                r_acc  += (float)abit;
            }
        }
    }

    // ---- flush: registers -> shared -> global (once per block) ----
    if (lane < N_BINS && r_cnt != 0.0f) {
        atomicAdd(&s_cnt[lane],  r_cnt);
        atomicAdd(&s_conf[lane], r_conf);
        atomicAdd(&s_acc[lane],  r_acc);
    }
    __syncthreads();
    if (tid < N_BINS) {
        float c = s_cnt[tid];
        if (c != 0.0f) {
            atomicAdd(&g_cnt[tid],  c);
            atomicAdd(&g_conf[tid], s_conf[tid]);
            atomicAdd(&g_acc[tid],  s_acc[tid]);
        }
    }
    __threadfence();
    __syncthreads();

    // ---- last block finalizes (fused; no second launch) ----
    if (tid == 0)
        s_last = (atomicAdd(&g_done, 1u) == gridDim.x - 1u);
    __syncthreads();
    if (s_last && tid == 0) {
        volatile float* vc = g_cnt;
        volatile float* vp = g_conf;
        volatile float* va = g_acc;
        float mce = -CUDART_INF_F;
        #pragma unroll
        for (int i = 0; i < N_BINS; i++) {
            float c    = vc[i];
            float prob = 0.0f, accu = 0.0f;
            if (c > 0.0f) {
                prob = vp[i] / c;
                accu = va[i] / c;
                float gap = fabsf(prob - accu);
                if (gap > mce) mce = gap;
            }
            out[1 + i]          = prob;
            out[1 + N_BINS + i] = accu;
            vc[i] = 0.0f; vp[i] = 0.0f; va[i] = 0.0f;   // reset for next replay
        }
        out[0] = mce;
        g_done = 0u;
    }
}

extern "C" void kernel_launch(void* const* d_in, const int* in_sizes, int n_in,
                              void* d_out, int out_size) {
    const float4* logits4 = (const float4*)d_in[0];
    const float*  logits  = (const float*)d_in[0];
    const int*    labels  = (const int*)d_in[1];
    int nrows = in_sizes[1];               // labels element count == N rows

    // 3 CTAs/SM (proven best in R5/R6 sweep); grid-stride over row groups
    mce_main_kernel<<<444, 256>>>(logits4, logits, labels, (float*)d_out, nrows);
}